// round 1
// baseline (speedup 1.0000x reference)
#include <cuda_runtime.h>
#include <math.h>

#define H     2048
#define E     64
#define KTOP  8
#define NTOK  16384
#define SEQ   4096
#define BATCH 4
#define MT    128
#define KC    32
#define NBLK  (NTOK / MT)   // 128 blocks, 32 per batch

// Deterministic per-block partials for the aux loss (fully overwritten each
// launch; no zeroing, no atomics -> bit-deterministic).
__device__ float g_ssum[NBLK][E];
__device__ float g_cnt [NBLK][E];

__global__ __launch_bounds__(256, 1)
void gate_kernel(const float* __restrict__ x,
                 const float* __restrict__ w,
                 float* __restrict__ out)
{
    // Shared memory: GEMM staging tiles, then (after last use) reuse the same
    // bytes for the 128x65 logits/scores array.
    __shared__ __align__(16) char sraw[MT * (E + 1) * 4];   // 33280 bytes
    float (*xs)[KC + 1] = reinterpret_cast<float(*)[KC + 1]>(sraw);            // 128x33
    float (*ws)[KC + 1] = reinterpret_cast<float(*)[KC + 1]>(sraw + MT * (KC + 1) * 4); // 64x33
    float (*ls)[E + 1]  = reinterpret_cast<float(*)[E + 1]>(sraw);             // 128x65
    __shared__ int cnt[E];

    const int tid = threadIdx.x;
    const int m0  = blockIdx.x * MT;
    const int tm  = tid >> 4;     // 0..15
    const int tn  = tid & 15;     // 0..15

    float acc[8][4];
#pragma unroll
    for (int i = 0; i < 8; i++)
#pragma unroll
        for (int j = 0; j < 4; j++) acc[i][j] = 0.f;

    // global load mapping: 256 threads, each loads float4s
    const int xr = tid >> 3;          // 0..31
    const int xc = (tid & 7) * 4;     // 0,4,...,28
    const float* xg = x + (size_t)m0 * H;

    float4 xreg[4], wreg[2];
#pragma unroll
    for (int p = 0; p < 4; p++)
        xreg[p] = *(const float4*)(xg + (size_t)(xr + p * 32) * H + xc);
#pragma unroll
    for (int p = 0; p < 2; p++)
        wreg[p] = *(const float4*)(w + (size_t)(xr + p * 32) * H + xc);

    for (int k0 = 0; k0 < H; k0 += KC) {
        // stage current chunk
#pragma unroll
        for (int p = 0; p < 4; p++) {
            int r = xr + p * 32;
            xs[r][xc + 0] = xreg[p].x; xs[r][xc + 1] = xreg[p].y;
            xs[r][xc + 2] = xreg[p].z; xs[r][xc + 3] = xreg[p].w;
        }
#pragma unroll
        for (int p = 0; p < 2; p++) {
            int r = xr + p * 32;
            ws[r][xc + 0] = wreg[p].x; ws[r][xc + 1] = wreg[p].y;
            ws[r][xc + 2] = wreg[p].z; ws[r][xc + 3] = wreg[p].w;
        }
        __syncthreads();

        // prefetch next chunk into registers (overlaps with FFMA below)
        const int k1 = k0 + KC;
        if (k1 < H) {
#pragma unroll
            for (int p = 0; p < 4; p++)
                xreg[p] = *(const float4*)(xg + (size_t)(xr + p * 32) * H + k1 + xc);
#pragma unroll
            for (int p = 0; p < 2; p++)
                wreg[p] = *(const float4*)(w + (size_t)(xr + p * 32) * H + k1 + xc);
        }

#pragma unroll
        for (int kk = 0; kk < KC; kk++) {
            float a[8], b[4];
#pragma unroll
            for (int i = 0; i < 8; i++) a[i] = xs[tm + 16 * i][kk];
#pragma unroll
            for (int j = 0; j < 4; j++) b[j] = ws[tn + 16 * j][kk];
#pragma unroll
            for (int i = 0; i < 8; i++)
#pragma unroll
                for (int j = 0; j < 4; j++)
                    acc[i][j] = fmaf(a[i], b[j], acc[i][j]);
        }
        __syncthreads();
    }

    // write logits into smem (strided micro-tile mapping)
#pragma unroll
    for (int i = 0; i < 8; i++)
#pragma unroll
        for (int j = 0; j < 4; j++)
            ls[tm + 16 * i][tn + 16 * j] = acc[i][j];
    if (tid < E) cnt[tid] = 0;
    __syncthreads();

    // per-token epilogue: softmax over 64 experts, top-8, renorm
    if (tid < MT) {
        float mx = -INFINITY;
#pragma unroll 8
        for (int e = 0; e < E; e++) mx = fmaxf(mx, ls[tid][e]);
        float s = 0.f;
#pragma unroll 8
        for (int e = 0; e < E; e++) {
            float v = expf(ls[tid][e] - mx);
            s += v;
            ls[tid][e] = v;
        }
        const float inv = 1.f / s;
#pragma unroll 8
        for (int e = 0; e < E; e++) ls[tid][e] *= inv;

        unsigned long long used = 0ull;
        float pw[KTOP];
        int   pi[KTOP];
        float tsum = 0.f;
#pragma unroll
        for (int k = 0; k < KTOP; k++) {
            float bs = -1.f;
            int   bi = 0;
            for (int e = 0; e < E; e++) {
                if ((used >> e) & 1ull) continue;
                float v = ls[tid][e];
                if (v > bs) { bs = v; bi = e; }   // strict '>' => lowest index on ties
            }
            used |= (1ull << bi);
            pw[k] = bs;
            pi[k] = bi;
            tsum += bs;
        }
        const float invw = 1.f / (tsum + 1e-20f);
        const size_t t = (size_t)m0 + tid;
#pragma unroll
        for (int k = 0; k < KTOP; k++) {
            out[t * KTOP + k]                       = (float)pi[k];
            out[(size_t)NTOK * KTOP + t * KTOP + k] = pw[k] * invw;
            atomicAdd(&cnt[pi[k]], 1);
        }
    }
    __syncthreads();

    // per-block deterministic partials: expert-wise score sums + counts
    if (tid < E) {
        float s = 0.f;
        for (int t = 0; t < MT; t++) s += ls[t][tid];
        g_ssum[blockIdx.x][tid] = s;
        g_cnt [blockIdx.x][tid] = (float)cnt[tid];
    }
}

__global__ void aux_kernel(float* __restrict__ out)
{
    __shared__ float part[E];
    const int e = threadIdx.x;   // 64 threads
    float acc = 0.f;
#pragma unroll
    for (int b = 0; b < BATCH; b++) {
        float ss = 0.f, cc = 0.f;
        for (int blk = 0; blk < NBLK / BATCH; blk++) {
            ss += g_ssum[b * (NBLK / BATCH) + blk][e];
            cc += g_cnt [b * (NBLK / BATCH) + blk][e];
        }
        float ce = cc * ((float)E / (float)(SEQ * KTOP));  // counts / 512
        float ms = ss * (1.f / (float)SEQ);
        acc += ce * ms;
    }
    part[e] = acc;
    __syncthreads();
    if (e == 0) {
        float t = 0.f;
        for (int i = 0; i < E; i++) t += part[i];
        out[2 * (size_t)NTOK * KTOP] = t * (1.f / (float)BATCH) * 0.1f;
    }
}

extern "C" void kernel_launch(void* const* d_in, const int* in_sizes, int n_in,
                              void* d_out, int out_size)
{
    const float* x = (const float*)d_in[0];   // hidden_states [4,4096,2048]
    const float* w = (const float*)d_in[1];   // weight        [64,2048]
    float* out = (float*)d_out;

    gate_kernel<<<NBLK, 256>>>(x, w, out);
    aux_kernel<<<1, E>>>(out);
}

// round 3
// speedup vs baseline: 1.2045x; 1.2045x over previous
#include <cuda_runtime.h>
#include <math.h>

#define H     2048
#define E     64
#define KTOP  8
#define NTOK  16384
#define SEQ   4096
#define BATCH 4
#define MT    128
#define KC    32
#define NBLK  (NTOK / MT)   // 128 blocks

#define PX    130           // xs_t row length (floats), even -> 8B-aligned rows
#define PW    66            // ws_t row length (floats), even

typedef unsigned long long ull;

#define FMA_F32X2(d, a, b, c) \
    asm("fma.rn.f32x2 %0, %1, %2, %3;" : "=l"(d) : "l"(a), "l"(b), "l"(c))

// Deterministic per-block partials for the aux loss.
__device__ float g_ssum[NBLK][E];
__device__ float g_cnt [NBLK][E];

__global__ __launch_bounds__(256, 1)
void gate_kernel(const float* __restrict__ x,
                 const float* __restrict__ w,
                 float* __restrict__ out)
{
    // K-transposed staging tiles; bytes reused afterwards for 128x65 scores.
    // xs_t: [KC][PX]  (k-major, token minor)  = 16640 B
    // ws_t: [KC][PW]  (k-major, expert minor) =  8448 B
    // wsw : [KC][PW]  lane-swapped experts    =  8448 B   total 33536 B
    __shared__ __align__(16) char sraw[(KC * PX + 2 * KC * PW) * 4];
    float (*xs)[PX]    = reinterpret_cast<float(*)[PX]>(sraw);
    float (*ws)[PW]    = reinterpret_cast<float(*)[PW]>(sraw + KC * PX * 4);
    float (*wsw)[PW]   = reinterpret_cast<float(*)[PW]>(sraw + (KC * PX + KC * PW) * 4);
    float (*ls)[E + 1] = reinterpret_cast<float(*)[E + 1]>(sraw);  // 33280 B, reuse
    __shared__ int cnt[E];

    const int tid = threadIdx.x;
    const int m0  = blockIdx.x * MT;
    const int tm  = tid >> 4;     // 0..15 -> token pairs tm+16i
    const int tn  = tid & 15;     // 0..15 -> expert pairs tn+16j

    // accD[i][j]: lanes (tok 2T, e 2E) / (tok 2T+1, e 2E+1)
    // accA[i][j]: lanes (tok 2T, e 2E+1) / (tok 2T+1, e 2E)
    ull accD[4][2], accA[4][2];
#pragma unroll
    for (int i = 0; i < 4; i++)
#pragma unroll
        for (int j = 0; j < 2; j++) { accD[i][j] = 0ull; accA[i][j] = 0ull; }

    // global load mapping: 256 threads, float4 each
    const int xr = tid >> 3;          // 0..31
    const int xc = (tid & 7) * 4;     // 0,4,...,28
    const float* xg = x + (size_t)m0 * H;

    float4 xreg[4], wreg[2];
#pragma unroll
    for (int p = 0; p < 4; p++)
        xreg[p] = *(const float4*)(xg + (size_t)(xr + p * 32) * H + xc);
#pragma unroll
    for (int p = 0; p < 2; p++)
        wreg[p] = *(const float4*)(w + (size_t)(xr + p * 32) * H + xc);

    for (int k0 = 0; k0 < H; k0 += KC) {
        // stage transposed: xs[k][token], ws[k][e], wsw[k][e^1]
#pragma unroll
        for (int p = 0; p < 4; p++) {
            int r = xr + p * 32;
            xs[xc + 0][r] = xreg[p].x; xs[xc + 1][r] = xreg[p].y;
            xs[xc + 2][r] = xreg[p].z; xs[xc + 3][r] = xreg[p].w;
        }
#pragma unroll
        for (int p = 0; p < 2; p++) {
            int e = xr + p * 32;
            ws[xc + 0][e] = wreg[p].x; ws[xc + 1][e] = wreg[p].y;
            ws[xc + 2][e] = wreg[p].z; ws[xc + 3][e] = wreg[p].w;
            int es = e ^ 1;
            wsw[xc + 0][es] = wreg[p].x; wsw[xc + 1][es] = wreg[p].y;
            wsw[xc + 2][es] = wreg[p].z; wsw[xc + 3][es] = wreg[p].w;
        }
        __syncthreads();

        const int k1 = k0 + KC;
        if (k1 < H) {
#pragma unroll
            for (int p = 0; p < 4; p++)
                xreg[p] = *(const float4*)(xg + (size_t)(xr + p * 32) * H + k1 + xc);
#pragma unroll
            for (int p = 0; p < 2; p++)
                wreg[p] = *(const float4*)(w + (size_t)(xr + p * 32) * H + k1 + xc);
        }

#pragma unroll 8
        for (int kk = 0; kk < KC; kk++) {
            ull a2[4], bD[2], bA[2];
#pragma unroll
            for (int i = 0; i < 4; i++)
                a2[i] = *(const ull*)&xs[kk][2 * (tm + 16 * i)];
#pragma unroll
            for (int j = 0; j < 2; j++) {
                bD[j] = *(const ull*)&ws [kk][2 * (tn + 16 * j)];
                bA[j] = *(const ull*)&wsw[kk][2 * (tn + 16 * j)];
            }
#pragma unroll
            for (int i = 0; i < 4; i++)
#pragma unroll
                for (int j = 0; j < 2; j++) {
                    FMA_F32X2(accD[i][j], a2[i], bD[j], accD[i][j]);
                    FMA_F32X2(accA[i][j], a2[i], bA[j], accA[i][j]);
                }
        }
        __syncthreads();
    }

    // scatter logits into smem (each lane is a clean sequential-k fp32 chain)
#pragma unroll
    for (int i = 0; i < 4; i++)
#pragma unroll
        for (int j = 0; j < 2; j++) {
            const int T = 2 * (tm + 16 * i);
            const int Eo = 2 * (tn + 16 * j);
            float dlo = __uint_as_float((unsigned)(accD[i][j] & 0xFFFFFFFFull));
            float dhi = __uint_as_float((unsigned)(accD[i][j] >> 32));
            float alo = __uint_as_float((unsigned)(accA[i][j] & 0xFFFFFFFFull));
            float ahi = __uint_as_float((unsigned)(accA[i][j] >> 32));
            ls[T][Eo]         = dlo;   // (2T, 2E)
            ls[T + 1][Eo + 1] = dhi;   // (2T+1, 2E+1)
            ls[T][Eo + 1]     = alo;   // (2T, 2E+1)
            ls[T + 1][Eo]     = ahi;   // (2T+1, 2E)
        }
    if (tid < E) cnt[tid] = 0;
    __syncthreads();

    // per-token epilogue: softmax over 64 experts, top-8, renorm
    if (tid < MT) {
        float mx = -INFINITY;
#pragma unroll 8
        for (int e = 0; e < E; e++) mx = fmaxf(mx, ls[tid][e]);
        float s = 0.f;
#pragma unroll 8
        for (int e = 0; e < E; e++) {
            float v = expf(ls[tid][e] - mx);
            s += v;
            ls[tid][e] = v;
        }
        const float inv = 1.f / s;
#pragma unroll 8
        for (int e = 0; e < E; e++) ls[tid][e] *= inv;

        unsigned long long used = 0ull;
        float pw[KTOP];
        int   pi[KTOP];
        float tsum = 0.f;
#pragma unroll
        for (int k = 0; k < KTOP; k++) {
            float bs = -1.f;
            int   bi = 0;
            for (int e = 0; e < E; e++) {
                if ((used >> e) & 1ull) continue;
                float v = ls[tid][e];
                if (v > bs) { bs = v; bi = e; }   // strict '>' => lowest index wins ties
            }
            used |= (1ull << bi);
            pw[k] = bs;
            pi[k] = bi;
            tsum += bs;
        }
        const float invw = 1.f / (tsum + 1e-20f);
        const size_t t = (size_t)m0 + tid;
#pragma unroll
        for (int k = 0; k < KTOP; k++) {
            out[t * KTOP + k]                       = (float)pi[k];
            out[(size_t)NTOK * KTOP + t * KTOP + k] = pw[k] * invw;
            atomicAdd(&cnt[pi[k]], 1);
        }
    }
    __syncthreads();

    // per-block deterministic partials
    if (tid < E) {
        float s = 0.f;
        for (int t = 0; t < MT; t++) s += ls[t][tid];
        g_ssum[blockIdx.x][tid] = s;
        g_cnt [blockIdx.x][tid] = (float)cnt[tid];
    }
}

__global__ __launch_bounds__(256, 1)
void aux_kernel(float* __restrict__ out)
{
    __shared__ float part[256];
    const int tid = threadIdx.x;
    const int b   = tid >> 6;     // batch 0..3
    const int e   = tid & 63;     // expert

    float ss = 0.f, cc = 0.f;
    const int base = b * (NBLK / BATCH);
#pragma unroll
    for (int blk = 0; blk < NBLK / BATCH; blk++) {
        ss += g_ssum[base + blk][e];
        cc += g_cnt [base + blk][e];
    }
    float ce = cc * ((float)E / (float)(SEQ * KTOP));
    float ms = ss * (1.f / (float)SEQ);
    part[tid] = ce * ms;
    __syncthreads();

#pragma unroll
    for (int stride = 128; stride > 0; stride >>= 1) {
        if (tid < stride) part[tid] += part[tid + stride];
        __syncthreads();
    }
    if (tid == 0)
        out[2 * (size_t)NTOK * KTOP] = part[0] * (0.1f / (float)BATCH);
}

extern "C" void kernel_launch(void* const* d_in, const int* in_sizes, int n_in,
                              void* d_out, int out_size)
{
    const float* x = (const float*)d_in[0];   // hidden_states [4,4096,2048]
    const float* w = (const float*)d_in[1];   // weight        [64,2048]
    float* out = (float*)d_out;

    gate_kernel<<<NBLK, 256>>>(x, w, out);
    aux_kernel<<<1, 256>>>(out);
}